// round 15
// baseline (speedup 1.0000x reference)
#include <cuda_runtime.h>
#include <math.h>

#define KNOTS 16
#define BOUNDF 5.0f
#define XD 6
#define CD 4
#define HID 128
#define SPL 47      // 3*KNOTS-1
#define LOW 3
#define OUTD 141    // LOW*SPL
#define OUTP 160    // padded: 8 col-groups x 20 cols (c0*4B = 80B, 16B-aligned)
#define TM 64
#define NTH 512
#define S1 66       // transposed stride (even -> 8B-aligned float2, conflict-free)

// shared layout (floats) — identical to the last PASSING kernel (R4, 1223us)
#define OFF_XS   0
#define OFF_CS   (OFF_XS + TM*XD)          // 384
#define OFF_LD   (OFF_CS + TM*CD)          // 640
#define OFF_BSH  (OFF_LD + TM*LOW)         // 832
#define OFF_WS   (OFF_BSH + OUTP)          // 992   (x4 = 3968, 16B aligned)
#define OFF_PT   (OFF_WS + HID*OUTP)       // 21472 (pt 160x66; h1t aliases it)
#define OFF_H1   OFF_PT
#define OFF_H2   (OFF_PT + OUTP*S1)        // 32032
#define OFF_Y    (OFF_H2 + HID*S1)         // 40480
#define SMEM_FLOATS (OFF_Y + TM*XD)        // 40864
#define SMEM_BYTES (SMEM_FLOATS * 4)       // 163456 — proven-passing size

typedef unsigned long long u64;

#define FMA2(d, a, b, c) \
    asm("fma.rn.f32x2 %0, %1, %2, %3;" : "=l"(d) : "l"(a), "l"(b), "l"(c))

__device__ __forceinline__ u64 pack2(float x, float y) {
    u64 r; asm("mov.b64 %0, {%1, %2};" : "=l"(r) : "f"(x), "f"(y)); return r;
}
__device__ __forceinline__ float2 unpack2(u64 v) {
    float2 f; asm("mov.b64 {%0, %1}, %2;" : "=f"(f.x), "=f"(f.y) : "l"(v)); return f;
}
__device__ __forceinline__ float softplus_f(float v) {
    return fmaxf(v, 0.0f) + log1pf(expf(-fabsf(v)));
}

__global__ __launch_bounds__(NTH, 1)
void nsc_kernel(const float* __restrict__ x, const float* __restrict__ c,
                const float* __restrict__ W1, const float* __restrict__ b1,
                const float* __restrict__ W2, const float* __restrict__ b2,
                const float* __restrict__ W3, const float* __restrict__ b3,
                float* __restrict__ y_out, float* __restrict__ ld_out, int N)
{
    extern __shared__ float sm[];
    float* xs  = sm + OFF_XS;
    float* cs  = sm + OFF_CS;
    float* ldsh= sm + OFF_LD;
    float* bsh = sm + OFF_BSH;
    float* ws  = sm + OFF_WS;
    float* h1t = sm + OFF_H1;   // [k][row] transposed (dead after phase 2)
    float* h2t = sm + OFF_H2;   // [k][row] transposed
    float* pt  = sm + OFF_PT;   // [col][row] transposed (aliases h1t)
    float* ysh = sm + OFF_Y;    // [row][6]

    const int tid  = threadIdx.x;
    const int base = blockIdx.x * TM;
    const int nrows = min(TM, N - base);

    const int w = tid >> 5, l = tid & 31;

    // ---- load inputs (zero-pad tail rows) + W1/b1 ----
    for (int i = tid; i < TM*XD; i += NTH) {
        int r = i / XD;
        xs[i] = (r < nrows) ? x[(size_t)(base + r)*XD + (i - r*XD)] : 0.0f;
    }
    for (int i = tid; i < TM*CD; i += NTH) {
        int r = i / CD;
        cs[i] = (r < nrows) ? c[(size_t)(base + r)*CD + (i - r*CD)] : 0.0f;
    }
    for (int i = tid; i < 7*HID; i += NTH) ws[i] = W1[i];
    for (int i = tid; i < HID; i += NTH)   bsh[i] = b1[i];
    __syncthreads();

    // ---- phase 1: h1t[j][r] = relu([upper, c] @ W1 + b1) ----
    for (int o = tid; o < TM*HID; o += NTH) {
        const int r = o & 63, j = o >> 6;   // j warp-uniform -> broadcast weight reads
        float acc = bsh[j];
        acc = fmaf(xs[r*XD+3], ws[0*HID+j], acc);
        acc = fmaf(xs[r*XD+4], ws[1*HID+j], acc);
        acc = fmaf(xs[r*XD+5], ws[2*HID+j], acc);
        acc = fmaf(cs[r*CD+0], ws[3*HID+j], acc);
        acc = fmaf(cs[r*CD+1], ws[4*HID+j], acc);
        acc = fmaf(cs[r*CD+2], ws[5*HID+j], acc);
        acc = fmaf(cs[r*CD+3], ws[6*HID+j], acc);
        h1t[j*S1 + r] = fmaxf(acc, 0.0f);
    }
    __syncthreads();

    // ---- load W2 (128x128) + b2 ----
    {
        const float4* src = (const float4*)W2;
        float4* dst = (float4*)ws;
        for (int i = tid; i < HID*HID/4; i += NTH) dst[i] = src[i];
    }
    for (int i = tid; i < HID; i += NTH) bsh[i] = b2[i];
    __syncthreads();

    // ---- phase 2: h2 = relu(h1 @ W2 + b2), FFMA2 (identical to passing R4) ----
    // 16 warps: warp w -> cols [8w, 8w+8); lane l -> rows 2l, 2l+1
    {
        const int c0 = w * 8;
        u64 accA[4], accB[4];   // A: row 2l, B: row 2l+1; pair = cols (2p, 2p+1)
        #pragma unroll
        for (int p = 0; p < 4; p++) {
            u64 bp = *(const u64*)&bsh[c0 + 2*p];
            accA[p] = bp; accB[p] = bp;
        }
        #pragma unroll 4
        for (int k = 0; k < HID; k++) {
            const float2 a = *(const float2*)&h1t[k*S1 + 2*l];
            const u64 axx = pack2(a.x, a.x);
            const u64 ayy = pack2(a.y, a.y);
            const ulonglong2 w01 = *(const ulonglong2*)&ws[k*HID + c0];
            const ulonglong2 w23 = *(const ulonglong2*)&ws[k*HID + c0 + 4];
            FMA2(accA[0], axx, w01.x, accA[0]); FMA2(accB[0], ayy, w01.x, accB[0]);
            FMA2(accA[1], axx, w01.y, accA[1]); FMA2(accB[1], ayy, w01.y, accB[1]);
            FMA2(accA[2], axx, w23.x, accA[2]); FMA2(accB[2], ayy, w23.x, accB[2]);
            FMA2(accA[3], axx, w23.y, accA[3]); FMA2(accB[3], ayy, w23.y, accB[3]);
        }
        #pragma unroll
        for (int p = 0; p < 4; p++) {
            float2 va = unpack2(accA[p]);   // cols (c0+2p, c0+2p+1), row 2l
            float2 vb = unpack2(accB[p]);   // same cols, row 2l+1
            va.x = fmaxf(va.x, 0.0f); va.y = fmaxf(va.y, 0.0f);
            vb.x = fmaxf(vb.x, 0.0f); vb.y = fmaxf(vb.y, 0.0f);
            *(u64*)&h2t[(c0 + 2*p    )*S1 + 2*l] = pack2(va.x, vb.x);
            *(u64*)&h2t[(c0 + 2*p + 1)*S1 + 2*l] = pack2(va.y, vb.y);
        }
    }
    __syncthreads();

    // ---- load W3 (128x141 -> padded 128x160) + b3 ----
    for (int i = tid; i < HID*OUTP; i += NTH) {
        int k = i / OUTP, j = i - k*OUTP;
        ws[i] = (j < OUTD) ? W3[k*OUTD + j] : 0.0f;
    }
    for (int i = tid; i < OUTP; i += NTH) bsh[i] = (i < OUTD) ? b3[i] : 0.0f;
    __syncthreads();

    // ---- phase 3 (CHANGED): p = h2 @ W3 + b3, LDS.128 weight broadcasts ----
    // 16 warps = 2 rowgroups x 8 colgroups; 1 row/lane, 20 cols/thread.
    // c0 = colg*20 -> 80B, 16B-aligned: weights as 5x ulonglong2 per k (was 10x LDS.64)
    {
        const int rowg = w >> 3, colg = w & 7;
        const int row  = rowg * 32 + l;
        const int c0   = colg * 20;
        u64 acc[10];
        #pragma unroll
        for (int p = 0; p < 10; p++) acc[p] = *(const u64*)&bsh[c0 + 2*p];

        const float* hp = &h2t[row];
        const float* wp = &ws[c0];
        #pragma unroll 2
        for (int k = 0; k < HID; k++) {
            const float av = hp[k * S1];           // 1 wavefront (32 consecutive rows)
            const u64 axx = pack2(av, av);
            const ulonglong2* wr = (const ulonglong2*)&wp[k * OUTP];  // broadcast
            const ulonglong2 q0 = wr[0], q1 = wr[1], q2 = wr[2], q3 = wr[3], q4 = wr[4];
            FMA2(acc[0], axx, q0.x, acc[0]); FMA2(acc[1], axx, q0.y, acc[1]);
            FMA2(acc[2], axx, q1.x, acc[2]); FMA2(acc[3], axx, q1.y, acc[3]);
            FMA2(acc[4], axx, q2.x, acc[4]); FMA2(acc[5], axx, q2.y, acc[5]);
            FMA2(acc[6], axx, q3.x, acc[6]); FMA2(acc[7], axx, q3.y, acc[7]);
            FMA2(acc[8], axx, q4.x, acc[8]); FMA2(acc[9], axx, q4.y, acc[9]);
        }
        #pragma unroll
        for (int p = 0; p < 10; p++) {
            const float2 v = unpack2(acc[p]);
            pt[(c0 + 2*p    )*S1 + row] = v.x;   // consecutive rows per warp: conflict-free
            pt[(c0 + 2*p + 1)*S1 + row] = v.y;
        }
    }
    __syncthreads();

    // ---- epilogue: RQS spline per (row, d); tid = d*64 + r (identical to R4) ----
    if (tid < TM*LOW) {
        const int r = tid & 63, d = tid >> 6;
        const float* p = &pt[(d*SPL)*S1 + r];   // param i at p[i*S1]

        float lw[KNOTS], lh[KNOTS];
        float mw = -1e30f, mh = -1e30f;
        #pragma unroll
        for (int i = 0; i < KNOTS; i++) {
            lw[i] = p[i*S1];           mw = fmaxf(mw, lw[i]);
            lh[i] = p[(KNOTS+i)*S1];   mh = fmaxf(mh, lh[i]);
        }
        float sw = 0.0f, sh = 0.0f;
        #pragma unroll
        for (int i = 0; i < KNOTS; i++) {
            lw[i] = expf(lw[i] - mw); sw += lw[i];
            lh[i] = expf(lh[i] - mh); sh += lh[i];
        }
        const float iw = (2.0f*BOUNDF) / sw, ih = (2.0f*BOUNDF) / sh;
        #pragma unroll
        for (int i = 0; i < KNOTS; i++) { lw[i] *= iw; lh[i] *= ih; }

        const float xv = xs[r*XD + d];
        const bool oob = (xv <= -BOUNDF) || (xv >= BOUNDF);
        const float xm = oob ? -BOUNDF : xv;

        float cumx = -BOUNDF, cumy = -BOUNDF;
        float xkb = 0.0f, ykb = 0.0f, wk = 1.0f, hk = 1.0f;
        int idx = 0; bool found = false;
        #pragma unroll
        for (int i = 0; i < KNOTS; i++) {
            float nx = cumx + lw[i];
            if (!found && (xm < nx || i == KNOTS-1)) {
                found = true; idx = i; xkb = cumx; ykb = cumy; wk = lw[i]; hk = lh[i];
            }
            cumx = nx; cumy += lh[i];
        }

        const float db = (idx == 0)        ? 1.0f : softplus_f(p[(2*KNOTS + idx - 1)*S1]);
        const float d1 = (idx == KNOTS-1)  ? 1.0f : softplus_f(p[(2*KNOTS + idx)*S1]);

        const float sk   = hk / wk;
        float relx = (xm - xkb) / wk;
        relx = fminf(fmaxf(relx, 0.0f), 1.0f);
        const float omr  = 1.0f - relx;
        const float r1v  = relx * omr;
        const float den  = sk + (d1 + db - 2.0f*sk) * r1v;
        const float num  = hk * (sk*relx*relx + db*r1v);
        float yv = ykb + num / den;
        float ld = 2.0f*logf(sk)
                 + logf(d1*relx*relx + 2.0f*sk*r1v + db*omr*omr)
                 - 2.0f*logf(den);
        if (oob) { yv = xv; ld = 0.0f; }

        ldsh[tid] = ld;
        ysh[r*XD + d] = yv;
    } else if (tid < 256) {
        // threads 192..255 copy through the upper dims for rows 0..63
        const int r = tid - 192;
        ysh[r*XD + 3] = xs[r*XD + 3];
        ysh[r*XD + 4] = xs[r*XD + 4];
        ysh[r*XD + 5] = xs[r*XD + 5];
    }
    __syncthreads();

    // ---- coalesced output ----
    for (int i = tid; i < nrows*XD; i += NTH)
        y_out[(size_t)base*XD + i] = ysh[i];
    if (tid < nrows)
        ld_out[base + tid] = ldsh[tid] + ldsh[64 + tid] + ldsh[128 + tid];
}

extern "C" void kernel_launch(void* const* d_in, const int* in_sizes, int n_in,
                              void* d_out, int out_size) {
    const float* x  = (const float*)d_in[0];
    const float* c  = (const float*)d_in[1];
    const float* W1 = (const float*)d_in[2];
    const float* b1 = (const float*)d_in[3];
    const float* W2 = (const float*)d_in[4];
    const float* b2 = (const float*)d_in[5];
    const float* W3 = (const float*)d_in[6];
    const float* b3 = (const float*)d_in[7];

    const int N = in_sizes[0] / XD;
    float* y    = (float*)d_out;
    float* ldet = y + (size_t)N * XD;

    cudaFuncSetAttribute(nsc_kernel, cudaFuncAttributeMaxDynamicSharedMemorySize, SMEM_BYTES);

    const int grid = (N + TM - 1) / TM;
    nsc_kernel<<<grid, NTH, SMEM_BYTES>>>(x, c, W1, b1, W2, b2, W3, b3, y, ldet, N);
}

// round 16
// speedup vs baseline: 1.2406x; 1.2406x over previous
#include <cuda_runtime.h>
#include <math.h>
#include <stdint.h>

#define KNOTS 16
#define BOUNDF 5.0f
#define XD 6
#define CD 4
#define HID 128
#define SPL 47
#define LOW 3
#define OUTD 141
#define OUTP 160     // padded W3 cols: 8 colgroups x 20 (80B, 16B-aligned)
#define TM 64
#define NTH 512
#define S1 66        // transposed activation stride
#define CH 16        // k-rows per weight chunk
#define NCH 8        // chunks per GEMM

// shared layout (float offsets), total 93568 B -> 2 CTAs/SM
#define OFF_XS   0          // 384
#define OFF_CS   384        // 256
#define OFF_LD   640        // 192
#define OFF_BSH  832        // 160
#define OFF_Y    992        // 384
#define OFF_WB0  1376       // 2560 floats (10240B), 16B-aligned
#define OFF_WB1  3936       // 2560
#define OFF_H1   6496       // 128*66 = 8448
#define OFF_H2   14944      // 8448
#define SMEM_FLOATS 23392
#define SMEM_BYTES (SMEM_FLOATS * 4)   // 93568
#define OFF_PT   OFF_H1     // pt[col*66+row], 141*66=9306 <= 16896 (h1t+h2t, dead)

typedef unsigned long long u64;
typedef uint32_t u32;

__device__ float g_W3pad[HID * OUTP];   // W3 padded to stride 160 (zeros beyond 141)

#define FMA2(d, a, b, c) \
    asm("fma.rn.f32x2 %0, %1, %2, %3;" : "=l"(d) : "l"(a), "l"(b), "l"(c))

__device__ __forceinline__ u64 pack2(float x, float y) {
    u64 r; asm("mov.b64 %0, {%1, %2};" : "=l"(r) : "f"(x), "f"(y)); return r;
}
__device__ __forceinline__ float2 unpack2(u64 v) {
    float2 f; asm("mov.b64 {%0, %1}, %2;" : "=f"(f.x), "=f"(f.y) : "l"(v)); return f;
}
__device__ __forceinline__ float softplus_f(float v) {
    return fmaxf(v, 0.0f) + log1pf(expf(-fabsf(v)));
}
__device__ __forceinline__ u32 smem_u32(const void* p) {
    u32 a; asm("{ .reg .u64 t; cvta.to.shared.u64 t, %1; cvt.u32.u64 %0, t; }" : "=r"(a) : "l"(p));
    return a;
}
__device__ __forceinline__ void cp16(u32 dst, const void* src) {
    asm volatile("cp.async.ca.shared.global [%0], [%1], 16;"
                 :: "r"(dst), "l"(__cvta_generic_to_global(src)));
}
#define CP_COMMIT() asm volatile("cp.async.commit_group;" ::: "memory")
#define CP_WAIT0()  asm volatile("cp.async.wait_group 0;" ::: "memory")

__global__ void w3pad_kernel(const float* __restrict__ W3) {
    int i = blockIdx.x * blockDim.x + threadIdx.x;
    if (i < HID * OUTP) {
        int k = i / OUTP, j = i - k * OUTP;
        g_W3pad[i] = (j < OUTD) ? W3[k * OUTD + j] : 0.0f;
    }
}

__global__ __launch_bounds__(NTH, 2)
void nsc_kernel(const float* __restrict__ x, const float* __restrict__ c,
                const float* __restrict__ W1, const float* __restrict__ b1,
                const float* __restrict__ W2, const float* __restrict__ b2,
                const float* __restrict__ b3,
                float* __restrict__ y_out, float* __restrict__ ld_out, int N)
{
    extern __shared__ float sm[];
    float* xs   = sm + OFF_XS;
    float* cs   = sm + OFF_CS;
    float* ldsh = sm + OFF_LD;
    float* bsh  = sm + OFF_BSH;
    float* ysh  = sm + OFF_Y;
    float* wb0  = sm + OFF_WB0;
    float* wb1  = sm + OFF_WB1;
    float* h1t  = sm + OFF_H1;
    float* h2t  = sm + OFF_H2;
    float* pt   = sm + OFF_PT;

    const int tid  = threadIdx.x;
    const int w    = tid >> 5, l = tid & 31;
    const int base = blockIdx.x * TM;
    const int nrows = min(TM, N - base);

    const u32 sb = smem_u32(sm);
    const u32 wb0a = sb + OFF_WB0 * 4;
    const u32 wb1a = sb + OFF_WB1 * 4;

    // ---- stage inputs + W1 (into wb0) + b1 ----
    for (int i = tid; i < TM * XD; i += NTH) {
        int r = i / XD;
        xs[i] = (r < nrows) ? x[(size_t)(base + r) * XD + (i - r * XD)] : 0.0f;
    }
    for (int i = tid; i < TM * CD; i += NTH) {
        int r = i / CD;
        cs[i] = (r < nrows) ? c[(size_t)(base + r) * CD + (i - r * CD)] : 0.0f;
    }
    for (int i = tid; i < 7 * HID; i += NTH) wb0[i] = W1[i];
    for (int i = tid; i < HID; i += NTH)     bsh[i] = b1[i];
    __syncthreads();

    // prefetch W2 chunk 0 -> wb1 (overlaps phase 1)
    cp16(wb1a + tid * 16, W2 + tid * 4);
    CP_COMMIT();

    // ---- phase 1: h1t[j][r] = relu([upper,c] @ W1 + b1) ----
    for (int o = tid; o < TM * HID; o += NTH) {
        const int r = o & 63, j = o >> 6;      // j warp-uniform -> broadcast
        float acc = bsh[j];
        acc = fmaf(xs[r*XD+3], wb0[0*HID+j], acc);
        acc = fmaf(xs[r*XD+4], wb0[1*HID+j], acc);
        acc = fmaf(xs[r*XD+5], wb0[2*HID+j], acc);
        acc = fmaf(cs[r*CD+0], wb0[3*HID+j], acc);
        acc = fmaf(cs[r*CD+1], wb0[4*HID+j], acc);
        acc = fmaf(cs[r*CD+2], wb0[5*HID+j], acc);
        acc = fmaf(cs[r*CD+3], wb0[6*HID+j], acc);
        h1t[j * S1 + r] = fmaxf(acc, 0.0f);
    }
    __syncthreads();
    for (int i = tid; i < HID; i += NTH) bsh[i] = b2[i];
    CP_WAIT0();
    __syncthreads();   // chunk0 + b2 + h1t all visible

    // ---- phase 2: h2 = relu(h1 @ W2 + b2); chunked weights, R4 inner loop ----
    // 16 warps: warp w -> cols [8w, 8w+8); lane l -> rows 2l, 2l+1
    {
        const int c0 = w * 8;
        u64 accA[4], accB[4];
        #pragma unroll
        for (int p = 0; p < 4; p++) {
            u64 bp = *(const u64*)&bsh[c0 + 2*p];
            accA[p] = bp; accB[p] = bp;
        }
        for (int ch = 0; ch < NCH; ch++) {
            if (ch < NCH - 1) {   // prefetch chunk ch+1 into buf[(ch+2)&1] (chunk j lives in buf[(j+1)&1])
                u32 dsta = ((ch & 1) ? wb1a : wb0a);
                cp16(dsta + tid * 16, W2 + (ch + 1) * (CH * HID) + tid * 4);
                CP_COMMIT();
            }
            const float* wb = ((ch & 1) ? wb0 : wb1);   // buf[(ch+1)&1]
            #pragma unroll 4
            for (int kk = 0; kk < CH; kk++) {
                const int k = ch * CH + kk;
                const float2 a = *(const float2*)&h1t[k * S1 + 2 * l];
                const u64 axx = pack2(a.x, a.x);
                const u64 ayy = pack2(a.y, a.y);
                const ulonglong2 w01 = *(const ulonglong2*)&wb[kk * HID + c0];
                const ulonglong2 w23 = *(const ulonglong2*)&wb[kk * HID + c0 + 4];
                FMA2(accA[0], axx, w01.x, accA[0]); FMA2(accB[0], ayy, w01.x, accB[0]);
                FMA2(accA[1], axx, w01.y, accA[1]); FMA2(accB[1], ayy, w01.y, accB[1]);
                FMA2(accA[2], axx, w23.x, accA[2]); FMA2(accB[2], ayy, w23.x, accB[2]);
                FMA2(accA[3], axx, w23.y, accA[3]); FMA2(accB[3], ayy, w23.y, accB[3]);
            }
            if (ch < NCH - 1) { CP_WAIT0(); __syncthreads(); }
        }
        #pragma unroll
        for (int p = 0; p < 4; p++) {
            float2 va = unpack2(accA[p]);
            float2 vb = unpack2(accB[p]);
            va.x = fmaxf(va.x, 0.0f); va.y = fmaxf(va.y, 0.0f);
            vb.x = fmaxf(vb.x, 0.0f); vb.y = fmaxf(vb.y, 0.0f);
            *(u64*)&h2t[(c0 + 2*p    ) * S1 + 2*l] = pack2(va.x, vb.x);
            *(u64*)&h2t[(c0 + 2*p + 1) * S1 + 2*l] = pack2(va.y, vb.y);
        }
    }

    // prefetch W3pad chunk 0 -> wb1 (chunk6 consumed; compute(7) used wb0)
    {
        cp16(wb1a + tid * 16, g_W3pad + tid * 4);
        if (tid + NTH < CH * OUTP / 4)
            cp16(wb1a + (tid + NTH) * 16, g_W3pad + (tid + NTH) * 4);
        CP_COMMIT();
    }
    __syncthreads();   // h2t stores visible; safe to overwrite bsh
    for (int i = tid; i < OUTP; i += NTH) bsh[i] = (i < OUTD) ? b3[i] : 0.0f;
    CP_WAIT0();
    __syncthreads();   // chunk0 + b3 visible

    // ---- phase 3: p = h2 @ W3 + b3; 2 rowg x 8 colg, 1 row/lane, 20 cols ----
    {
        const int rowg = w >> 3, colg = w & 7;
        const int row  = rowg * 32 + l;
        const int c0   = colg * 20;
        u64 acc[10];
        #pragma unroll
        for (int p = 0; p < 10; p++) acc[p] = *(const u64*)&bsh[c0 + 2*p];

        for (int ch = 0; ch < NCH; ch++) {
            if (ch < NCH - 1) {
                u32 dsta = ((ch & 1) ? wb1a : wb0a);
                const float* src = g_W3pad + (ch + 1) * (CH * OUTP);
                cp16(dsta + tid * 16, src + tid * 4);
                if (tid + NTH < CH * OUTP / 4)
                    cp16(dsta + (tid + NTH) * 16, src + (tid + NTH) * 4);
                CP_COMMIT();
            }
            const float* wb = ((ch & 1) ? wb0 : wb1);
            #pragma unroll 2
            for (int kk = 0; kk < CH; kk++) {
                const int k = ch * CH + kk;
                const float av = h2t[k * S1 + row];
                const u64 axx = pack2(av, av);
                const ulonglong2* wr = (const ulonglong2*)&wb[kk * OUTP + c0];
                const ulonglong2 q0 = wr[0], q1 = wr[1], q2 = wr[2], q3 = wr[3], q4 = wr[4];
                FMA2(acc[0], axx, q0.x, acc[0]); FMA2(acc[1], axx, q0.y, acc[1]);
                FMA2(acc[2], axx, q1.x, acc[2]); FMA2(acc[3], axx, q1.y, acc[3]);
                FMA2(acc[4], axx, q2.x, acc[4]); FMA2(acc[5], axx, q2.y, acc[5]);
                FMA2(acc[6], axx, q3.x, acc[6]); FMA2(acc[7], axx, q3.y, acc[7]);
                FMA2(acc[8], axx, q4.x, acc[8]); FMA2(acc[9], axx, q4.y, acc[9]);
            }
            if (ch < NCH - 1) { CP_WAIT0(); __syncthreads(); }
        }
        __syncthreads();   // all h2t reads done -> pt may alias h1t/h2t
        #pragma unroll
        for (int p = 0; p < 10; p++) {
            const int col = c0 + 2*p;
            const float2 v = unpack2(acc[p]);
            if (col < OUTD)     pt[(col    ) * S1 + row] = v.x;
            if (col + 1 < OUTD) pt[(col + 1) * S1 + row] = v.y;
        }
    }
    __syncthreads();

    // ---- epilogue: RQS spline per (row, d); tid = d*64 + r ----
    if (tid < TM * LOW) {
        const int r = tid & 63, d = tid >> 6;
        const float* p = &pt[(d * SPL) * S1 + r];   // param i at p[i*S1]

        float lw[KNOTS], lh[KNOTS];
        float mw = -1e30f, mh = -1e30f;
        #pragma unroll
        for (int i = 0; i < KNOTS; i++) {
            lw[i] = p[i * S1];           mw = fmaxf(mw, lw[i]);
            lh[i] = p[(KNOTS + i) * S1]; mh = fmaxf(mh, lh[i]);
        }
        float sw = 0.0f, sh = 0.0f;
        #pragma unroll
        for (int i = 0; i < KNOTS; i++) {
            lw[i] = expf(lw[i] - mw); sw += lw[i];
            lh[i] = expf(lh[i] - mh); sh += lh[i];
        }
        const float iw = (2.0f * BOUNDF) / sw, ih = (2.0f * BOUNDF) / sh;
        #pragma unroll
        for (int i = 0; i < KNOTS; i++) { lw[i] *= iw; lh[i] *= ih; }

        const float xv = xs[r * XD + d];
        const bool oob = (xv <= -BOUNDF) || (xv >= BOUNDF);
        const float xm = oob ? -BOUNDF : xv;

        float cumx = -BOUNDF, cumy = -BOUNDF;
        float xkb = 0.0f, ykb = 0.0f, wk = 1.0f, hk = 1.0f;
        int idx = 0; bool found = false;
        #pragma unroll
        for (int i = 0; i < KNOTS; i++) {
            const float nx = cumx + lw[i];
            if (!found && (xm < nx || i == KNOTS - 1)) {
                found = true; idx = i; xkb = cumx; ykb = cumy; wk = lw[i]; hk = lh[i];
            }
            cumx = nx; cumy += lh[i];
        }

        const float db = (idx == 0)         ? 1.0f : softplus_f(p[(2 * KNOTS + idx - 1) * S1]);
        const float d1 = (idx == KNOTS - 1) ? 1.0f : softplus_f(p[(2 * KNOTS + idx) * S1]);

        const float sk = hk / wk;
        float relx = (xm - xkb) / wk;
        relx = fminf(fmaxf(relx, 0.0f), 1.0f);
        const float omr = 1.0f - relx;
        const float r1v = relx * omr;
        const float den = sk + (d1 + db - 2.0f * sk) * r1v;
        const float num = hk * (sk * relx * relx + db * r1v);
        float yv = ykb + num / den;
        float ld = 2.0f * logf(sk)
                 + logf(d1 * relx * relx + 2.0f * sk * r1v + db * omr * omr)
                 - 2.0f * logf(den);
        if (oob) { yv = xv; ld = 0.0f; }

        ldsh[tid] = ld;
        ysh[r * XD + d] = yv;
    } else if (tid < 256) {
        const int r = tid - 192;    // copy-through upper dims
        ysh[r * XD + 3] = xs[r * XD + 3];
        ysh[r * XD + 4] = xs[r * XD + 4];
        ysh[r * XD + 5] = xs[r * XD + 5];
    }
    __syncthreads();

    // ---- coalesced output ----
    for (int i = tid; i < nrows * XD; i += NTH)
        y_out[(size_t)base * XD + i] = ysh[i];
    if (tid < nrows)
        ld_out[base + tid] = ldsh[tid] + ldsh[64 + tid] + ldsh[128 + tid];
}

extern "C" void kernel_launch(void* const* d_in, const int* in_sizes, int n_in,
                              void* d_out, int out_size) {
    const float* x  = (const float*)d_in[0];
    const float* c  = (const float*)d_in[1];
    const float* W1 = (const float*)d_in[2];
    const float* b1 = (const float*)d_in[3];
    const float* W2 = (const float*)d_in[4];
    const float* b2 = (const float*)d_in[5];
    const float* W3 = (const float*)d_in[6];
    const float* b3 = (const float*)d_in[7];

    const int N = in_sizes[0] / XD;
    float* y    = (float*)d_out;
    float* ldet = y + (size_t)N * XD;

    w3pad_kernel<<<(HID * OUTP + 255) / 256, 256>>>(W3);

    cudaFuncSetAttribute(nsc_kernel, cudaFuncAttributeMaxDynamicSharedMemorySize, SMEM_BYTES);
    const int grid = (N + TM - 1) / TM;
    nsc_kernel<<<grid, NTH, SMEM_BYTES>>>(x, c, W1, b1, W2, b2, b3, y, ldet, N);
}